// round 5
// baseline (speedup 1.0000x reference)
#include <cuda_runtime.h>

#define N_ELEC 62
#define IN_CH  5
#define HID    32
#define N_CLS  3
#define SPITCH 64          // padded row stride for S / A
#define GPB    8           // graphs per block (4 f32x2 pairs)
#define NPAIR  (GPB/2)
#define NTHR   512

// Precomputed S = M^2, M = D^{-1/2} A D^{-1/2}; padded [62][64], cols 62..63 = 0
__device__ float g_S[N_ELEC * SPITCH];

#define FMA2(acc, a, b) \
    asm("fma.rn.f32x2 %0, %1, %2, %0;" : "+l"(acc) : "l"(a), "l"(b))
#define ADD2(acc, v) \
    asm("add.rn.f32x2 %0, %0, %1;" : "+l"(acc) : "l"(v))
#define PACK2(d, s) \
    asm("mov.b64 %0, {%1, %1};" : "=l"(d) : "f"(s))
#define UNPK2(lo, hi, v) \
    asm("mov.b64 {%0, %1}, %2;" : "=f"(lo), "=f"(hi) : "l"(v))

// ---------------------------------------------------------------------------
// Setup: grid = 62 blocks, block i computes row i of S = M @ M.
// S[i][j] = dinv[j] * sum_k (dinv[i]*dinv[k]^2*A[i][k]) * A[k][j]
// ---------------------------------------------------------------------------
__global__ __launch_bounds__(128) void rgnn_setup_kernel(
    const float* __restrict__ adj_tril)
{
    __shared__ float A[N_ELEC * SPITCH];
    __shared__ float dinv[N_ELEC];
    __shared__ float t[N_ELEC];
    const int tid = threadIdx.x;
    const int i   = blockIdx.x;

    for (int idx = tid; idx < N_ELEC * N_ELEC; idx += 128) {
        int r = idx / N_ELEC, c = idx % N_ELEC;
        int a = r > c ? r : c;
        int b = r > c ? c : r;
        A[r * SPITCH + c] = adj_tril[a * (a + 1) / 2 + b];
    }
    __syncthreads();

    if (tid < N_ELEC) {
        float d = 0.f;
        #pragma unroll 2
        for (int c = 0; c < N_ELEC; c++) d += fabsf(A[tid * SPITCH + c]);
        dinv[tid] = (d > 0.f) ? rsqrtf(d) : 0.f;
    }
    __syncthreads();

    if (tid < N_ELEC) {
        float dk = dinv[tid];
        t[tid] = dinv[i] * dk * dk * A[i * SPITCH + tid];
    }
    __syncthreads();

    if (tid < SPITCH) {
        const int j = tid;
        float s = 0.f;
        if (j < N_ELEC) {
            #pragma unroll 2
            for (int k = 0; k < N_ELEC; k++)
                s = fmaf(t[k], A[k * SPITCH + j], s);
            s *= dinv[j];
        }
        g_S[i * SPITCH + j] = s;         // pad cols 62..63 get 0
    }
}

// ---------------------------------------------------------------------------
// Main: phase A = pair-packed propagation split across 2 i-halves;
// phase B = two warps per graph: relu(Wy+b) -> pool -> fc.
// ---------------------------------------------------------------------------
__global__ __launch_bounds__(NTHR) void rgnn_main_kernel(
    const float* __restrict__ x, const float* __restrict__ lin_w,
    const float* __restrict__ lin_b, const float* __restrict__ fc_w,
    const float* __restrict__ fc_b, float* __restrict__ out, int B)
{
    // phase A: Ssh [62*64] (15872B) | Xp [NPAIR][62][6] float2 (11904B)
    // phase B: Ysh [GPB][5][64] (10240B) aliases the Ssh region
    __shared__ __align__(16) float smem[N_ELEC * SPITCH + NPAIR * N_ELEC * 6 * 2];
    float*  Ssh = smem;
    float2* Xp  = (float2*)(smem + N_ELEC * SPITCH);
    float*  Ysh = smem;
    __shared__ __align__(16) unsigned long long scr[NPAIR * IN_CH * 64]; // 10240B
    __shared__ float Wsh[HID][IN_CH];
    __shared__ float bsh[HID];
    __shared__ float Fsh[N_CLS][HID];
    __shared__ float fcb[N_CLS];
    __shared__ float red[GPB][2][N_CLS];

    const int tid = threadIdx.x;
    const int g0  = blockIdx.x * GPB;

    // ---- stage S (float4), small weights, X (pair-interleaved) ----
    {
        const float4* gs4 = (const float4*)g_S;
        float4* ss4 = (float4*)Ssh;
        for (int idx = tid; idx < N_ELEC * SPITCH / 4; idx += NTHR)
            ss4[idx] = gs4[idx];
    }
    for (int idx = tid; idx < HID * IN_CH + HID + N_CLS * HID + N_CLS; idx += NTHR) {
        if (idx < 160)      ((float*)Wsh)[idx] = lin_w[idx];
        else if (idx < 192) bsh[idx - 160] = lin_b[idx - 160];
        else if (idx < 288) ((float*)Fsh)[idx - 192] = fc_w[idx - 192];
        else                fcb[idx - 288] = fc_b[idx - 288];
    }
    {
        const float* xg = x + (size_t)g0 * N_ELEC * IN_CH;
        const int nv = (B - g0) < GPB ? (B - g0) : GPB;
        const int total = nv * N_ELEC * IN_CH;
        for (int idx = tid; idx < total; idx += NTHR) {
            int g = idx / (N_ELEC * IN_CH);
            int r = idx % (N_ELEC * IN_CH);
            int i = r / IN_CH, c = r % IN_CH;
            ((float*)&Xp[((g >> 1) * N_ELEC + i) * 6 + c])[g & 1] = xg[idx];
        }
    }
    __syncthreads();

    // ---- phase A: y_j = sum_i S[i][j] * x_i ; thread = (h, pair, j) ----
    const int j = tid & 63;
    const int p = (tid >> 6) & 3;        // pair -> graphs 2p, 2p+1
    const int h = tid >> 8;              // i-half: 0 -> i<31, 1 -> i>=31
    unsigned long long a0=0,a1=0,a2=0,a3=0,a4=0;

    if (j < N_ELEC) {
        const unsigned xb = (unsigned)__cvta_generic_to_shared(&Xp[p * N_ELEC * 6]);
        const int ibeg = h * 31;
        #pragma unroll 1
        for (int i = ibeg; i < ibeg + 31; i++) {
            float s = Ssh[i * SPITCH + j];             // stride-1, conflict-free
            unsigned long long s2; PACK2(s2, s);
            unsigned long long q0,q1,q2,q3,q4;
            unsigned a = xb + i * 48;                  // broadcast
            asm("ld.shared.v2.u64 {%0,%1}, [%2];"    : "=l"(q0), "=l"(q1) : "r"(a));
            asm("ld.shared.v2.u64 {%0,%1}, [%2+16];" : "=l"(q2), "=l"(q3) : "r"(a));
            asm("ld.shared.u64 %0, [%1+32];"         : "=l"(q4)           : "r"(a));
            FMA2(a0,s2,q0); FMA2(a1,s2,q1); FMA2(a2,s2,q2); FMA2(a3,s2,q3); FMA2(a4,s2,q4);
        }
    }

    // combine halves: h=1 stores partials (layout [p][c][j]: conflict-free)
    if (h == 1) {
        unsigned long long* sp = &scr[(p * IN_CH) * 64 + j];
        sp[0]   = a0;  sp[64]  = a1;  sp[128] = a2;  sp[192] = a3;  sp[256] = a4;
    }
    __syncthreads();   // also retires all Ssh/Xp reads -> region reusable

    if (h == 0) {
        const unsigned long long* sp = &scr[(p * IN_CH) * 64 + j];
        ADD2(a0, sp[0]);   ADD2(a1, sp[64]);  ADD2(a2, sp[128]);
        ADD2(a3, sp[192]); ADD2(a4, sp[256]);
        float lo, hi;
        if (j < N_ELEC) {
            #define YW(acc, c) \
                UNPK2(lo, hi, acc); \
                Ysh[(2*p)   * 320 + (c) * 64 + j] = lo; \
                Ysh[(2*p+1) * 320 + (c) * 64 + j] = hi;
            YW(a0, 0) YW(a1, 1) YW(a2, 2) YW(a3, 3) YW(a4, 4)
            #undef YW
        } else {
            #pragma unroll
            for (int c = 0; c < IN_CH; c++) {          // zero pads j = 62, 63
                Ysh[(2*p)   * 320 + c * 64 + j] = 0.f;
                Ysh[(2*p+1) * 320 + c * 64 + j] = 0.f;
            }
        }
    }
    __syncthreads();

    // ---- phase B: 2 warps per graph, lane = hidden unit o ----
    const int o    = tid & 31;
    const int warp = tid >> 5;           // 0..15
    const int g    = warp >> 1;          // 0..7
    const int half = warp & 1;           // j range half
    const float w0 = Wsh[o][0], w1 = Wsh[o][1], w2 = Wsh[o][2],
                w3 = Wsh[o][3], w4 = Wsh[o][4];
    unsigned long long wd0,wd1,wd2,wd3,wd4,bd;
    PACK2(wd0,w0); PACK2(wd1,w1); PACK2(wd2,w2); PACK2(wd3,w3); PACK2(wd4,w4);
    PACK2(bd, bsh[o]);
    const float f0 = Fsh[0][o], f1 = Fsh[1][o], f2 = Fsh[2][o];

    {
        const unsigned yb = (unsigned)__cvta_generic_to_shared(&Ysh[g * 320])
                            + half * 128;              // j offset 32
        float ph = 0.f;
        #pragma unroll 4
        for (int k = 0; k < 16; k++) {                 // 16 j-pairs per warp
            unsigned long long y0,y1,y2,y3,y4;
            unsigned a = yb + k * 8;
            asm("ld.shared.u64 %0, [%1];"      : "=l"(y0) : "r"(a));
            asm("ld.shared.u64 %0, [%1+256];"  : "=l"(y1) : "r"(a));
            asm("ld.shared.u64 %0, [%1+512];"  : "=l"(y2) : "r"(a));
            asm("ld.shared.u64 %0, [%1+768];"  : "=l"(y3) : "r"(a));
            asm("ld.shared.u64 %0, [%1+1024];" : "=l"(y4) : "r"(a));
            unsigned long long v = bd;
            FMA2(v, wd0, y0); FMA2(v, wd1, y1); FMA2(v, wd2, y2);
            FMA2(v, wd3, y3); FMA2(v, wd4, y4);
            float lo, hi; UNPK2(lo, hi, v);
            ph += fmaxf(lo, 0.f);
            ph += fmaxf(hi, 0.f);
        }
        float s0 = f0 * ph, s1 = f1 * ph, s2 = f2 * ph;
        #pragma unroll
        for (int off = 16; off > 0; off >>= 1) {
            s0 += __shfl_down_sync(0xffffffffu, s0, off);
            s1 += __shfl_down_sync(0xffffffffu, s1, off);
            s2 += __shfl_down_sync(0xffffffffu, s2, off);
        }
        if (o == 0) {
            red[g][half][0] = s0;
            red[g][half][1] = s1;
            red[g][half][2] = s2;
        }
    }
    __syncthreads();

    if (tid < GPB * N_CLS) {
        const int gg = tid / N_CLS, c = tid % N_CLS;
        if (g0 + gg < B)
            out[(size_t)(g0 + gg) * N_CLS + c] =
                red[gg][0][c] + red[gg][1][c] + fcb[c];
    }
}

// ---------------------------------------------------------------------------
extern "C" void kernel_launch(void* const* d_in, const int* in_sizes, int n_in,
                              void* d_out, int out_size) {
    const float* x        = (const float*)d_in[0];
    const float* adj_tril = (const float*)d_in[1];
    const float* lin_w    = (const float*)d_in[2];
    const float* lin_b    = (const float*)d_in[3];
    const float* fc_w     = (const float*)d_in[4];
    const float* fc_b     = (const float*)d_in[5];
    // d_in[6] edge_index / d_in[7] batch_idx are structurally redundant.

    const int B = in_sizes[0] / (N_ELEC * IN_CH);

    rgnn_setup_kernel<<<N_ELEC, 128>>>(adj_tril);

    const int grid = (B + GPB - 1) / GPB;
    rgnn_main_kernel<<<grid, NTHR>>>(x, lin_w, lin_b, fc_w, fc_b,
                                     (float*)d_out, B);
}